// round 16
// baseline (speedup 1.0000x reference)
#include <cuda_runtime.h>
#include <cuda_fp16.h>
#include <cstdint>
#include <math.h>

#define BATCH 8
#define SEQ   4096
#define DIM   64
#define TQ    128
#define TK    128
#define NTILE (SEQ / TK)

#define BUFB  16384              // per K buffer: 128 rows x 128B fp16
#define QSTG  (4 * BUFB)         // Q staging after the 4 K buffers
#define SMEM_BYTES (4 * BUFB + 16384)   // 81920 -> 2 CTAs/SM

#define L2E 1.44269504f

__device__ __align__(16) __half g_xh[BATCH * SEQ * DIM];   // fp16(X)
__device__ float g_qn[BATCH * SEQ];

static __device__ __forceinline__ uint32_t smem_u32(const void* p) {
    uint32_t a;
    asm("{ .reg .u64 t; cvta.to.shared.u64 t, %1; cvt.u32.u64 %0, t; }" : "=r"(a) : "l"(p));
    return a;
}
static __device__ __forceinline__ void cp16(uint32_t dst, const void* src) {
    asm volatile("cp.async.cg.shared.global [%0], [%1], 16;" :: "r"(dst), "l"(src) : "memory");
}
#define CP_COMMIT() asm volatile("cp.async.commit_group;" ::: "memory")
#define CP_WAIT(n)  asm volatile("cp.async.wait_group %0;" :: "n"(n) : "memory")

static __device__ __forceinline__ void ldsm_x4(uint32_t (&r)[4], uint32_t a) {
    asm volatile("ldmatrix.sync.aligned.m8n8.x4.shared.b16 {%0,%1,%2,%3}, [%4];"
                 : "=r"(r[0]), "=r"(r[1]), "=r"(r[2]), "=r"(r[3]) : "r"(a));
}
static __device__ __forceinline__ void ldsm_x4_t(uint32_t (&r)[4], uint32_t a) {
    asm volatile("ldmatrix.sync.aligned.m8n8.x4.trans.shared.b16 {%0,%1,%2,%3}, [%4];"
                 : "=r"(r[0]), "=r"(r[1]), "=r"(r[2]), "=r"(r[3]) : "r"(a));
}
static __device__ __forceinline__ void mma_f16(float (&d)[4], const uint32_t (&a)[4],
                                               uint32_t b0, uint32_t b1) {
    asm volatile("mma.sync.aligned.m16n8k16.row.col.f32.f16.f16.f32 "
                 "{%0,%1,%2,%3}, {%4,%5,%6,%7}, {%8,%9}, {%0,%1,%2,%3};"
                 : "+f"(d[0]), "+f"(d[1]), "+f"(d[2]), "+f"(d[3])
                 : "r"(a[0]), "r"(a[1]), "r"(a[2]), "r"(a[3]), "r"(b0), "r"(b1));
}
static __device__ __forceinline__ float ex2f(float z) {
    float p;
    asm("ex2.approx.f32 %0, %1;" : "=f"(p) : "f"(z));
    return p;
}
static __device__ __forceinline__ uint32_t pack_h2(float a, float b) {
    __half2 h = __float22half2_rn(make_float2(a, b));
    return *reinterpret_cast<uint32_t*>(&h);
}

// ---- Pre-pass: X -> fp16 + row norms. 8 threads/row. ----
__global__ void prep_kernel(const float* __restrict__ X) {
    int t = blockIdx.x * 256 + threadIdx.x;
    int ln = t & 7;
    const float4* p = (const float4*)(X + (size_t)(t >> 3) * DIM) + ln * 2;
    float4 a = p[0], b = p[1];
    uint32_t h0 = pack_h2(a.x, a.y), h1 = pack_h2(a.z, a.w);
    uint32_t h2 = pack_h2(b.x, b.y), h3 = pack_h2(b.z, b.w);
    ((uint2*)g_xh)[2*t]   = make_uint2(h0, h1);
    ((uint2*)g_xh)[2*t+1] = make_uint2(h2, h3);
    float s = a.x*a.x + a.y*a.y + a.z*a.z + a.w*a.w
            + b.x*b.x + b.y*b.y + b.z*b.z + b.w*b.w;
    s += __shfl_xor_sync(0xffffffffu, s, 1, 8);
    s += __shfl_xor_sync(0xffffffffu, s, 2, 8);
    s += __shfl_xor_sync(0xffffffffu, s, 4, 8);
    if (ln == 0) g_qn[t >> 3] = s;
}

// stage one K tile (16KB fp16, 128 rows) via cp.async; 4 chunks/thread
static __device__ __forceinline__ void stage_k(uint32_t buf, const __half* xh_b,
                                               int kt, int tid) {
    #pragma unroll
    for (int k = 0; k < 4; k++) {
        int cid = tid + k * 256;
        int row = cid >> 3, c = cid & 7;
        uint32_t doff = (uint32_t)(row * 128 + ((c ^ (row & 7)) << 4));
        size_t soff = (size_t)(kt + row) * 128 + c * 16;
        cp16(buf + doff, (const char*)xh_b + soff);
    }
}

struct Ctx {
    uint32_t buf, kb_row, vb_row;
    uint32_t kch[4], vch[4];
    const uint32_t (*QH)[4];
};

// S = Q K^T for quarter h (rows h*32..h*32+31 of the 128-row tile)
static __device__ __forceinline__ void compute_S(const Ctx& c, int h, float (&S)[4][4]) {
    #pragma unroll
    for (int i = 0; i < 4; i++)
        #pragma unroll
        for (int j = 0; j < 4; j++) S[i][j] = 0.f;
    #pragma unroll
    for (int kc = 0; kc < 4; kc++) {
        #pragma unroll
        for (int j2 = 0; j2 < 2; j2++) {
            int j = 2 * h + j2;
            uint32_t a = c.buf + c.kb_row + (uint32_t)(j * 2048) + c.kch[kc];
            uint32_t bh[4];
            ldsm_x4(bh, a);
            mma_f16(S[2*j2],   c.QH[kc], bh[0], bh[1]);
            mma_f16(S[2*j2+1], c.QH[kc], bh[2], bh[3]);
        }
    }
}

// p = exp2(fma(s, L2E, -m*L2E)) -> fp16; l accumulates fp32 exps
static __device__ __forceinline__ void softmax_q(const float (&S)[4][4], float nm0, float nm1,
                                                 float& l0, float& l1, uint32_t (&PH)[4][2]) {
    #pragma unroll
    for (int jb = 0; jb < 4; jb++) {
        float e0 = ex2f(fmaf(S[jb][0], L2E, nm0));
        float e1 = ex2f(fmaf(S[jb][1], L2E, nm0));
        float e2 = ex2f(fmaf(S[jb][2], L2E, nm1));
        float e3 = ex2f(fmaf(S[jb][3], L2E, nm1));
        l0 += e0 + e1;
        l1 += e2 + e3;
        PH[jb][0] = pack_h2(e0, e1);
        PH[jb][1] = pack_h2(e2, e3);
    }
}

// O += P * V for quarter h
static __device__ __forceinline__ void compute_O(const Ctx& c, int h,
                                                 const uint32_t (&PH)[4][2], float (&O)[8][4]) {
    #pragma unroll
    for (int n2 = 0; n2 < 2; n2++) {
        int nc = 2 * h + n2;
        uint32_t pah[4] = {PH[2*n2][0], PH[2*n2][1], PH[2*n2+1][0], PH[2*n2+1][1]};
        #pragma unroll
        for (int cp = 0; cp < 4; cp++) {
            uint32_t a = c.buf + c.vb_row + (uint32_t)(nc * 2048) + c.vch[cp];
            uint32_t bh[4];
            ldsm_x4_t(bh, a);
            mma_f16(O[2*cp],   pah, bh[0], bh[1]);
            mma_f16(O[2*cp+1], pah, bh[2], bh[3]);
        }
    }
}

static __device__ __forceinline__ void quarter(const Ctx& c, int h, float nm0, float nm1,
                                               float& l0, float& l1, float (&O)[8][4]) {
    float S[4][4];
    uint32_t PH[4][2];
    compute_S(c, h, S);
    softmax_q(S, nm0, nm1, l0, l1, PH);
    compute_O(c, h, PH, O);
}

__global__ __launch_bounds__(256, 2)
void attn_hmma_kernel(const float* __restrict__ X, float* __restrict__ Y) {
    extern __shared__ char smc[];
    const uint32_t smb = smem_u32(smc);

    const int tid  = threadIdx.x;
    const int wid  = tid >> 5;
    const int lane = tid & 31;
    const int q2   = lane >> 3;
    const int rr   = lane & 7;
    const int g    = lane >> 2;
    const int sg   = lane & 3;
    const int wg   = wid >> 2;

    const int b  = blockIdx.y;
    const int q0 = blockIdx.x * TQ;
    const __half* xh_b = g_xh + (size_t)b * SEQ * DIM;

    const float nm0 = -g_qn[b * SEQ + q0 + wid * 16 + g] * L2E;
    const float nm1 = -g_qn[b * SEQ + q0 + wid * 16 + g + 8] * L2E;

    // ---- Stage Q tile (16KB) ----
    const uint32_t qstage = smb + QSTG;
    #pragma unroll
    for (int k = 0; k < 4; k++) {
        int cid = tid + k * 256;
        int row = cid >> 3, c = cid & 7;
        uint32_t doff = (uint32_t)(row * 128 + ((c ^ (row & 7)) << 4));
        size_t soff = (size_t)(q0 + row) * 128 + c * 16;
        cp16(qstage + doff, (const char*)xh_b + soff);
    }
    CP_COMMIT();

    // ---- Preload K tiles 0..2 ----
    stage_k(smb + 0 * BUFB, xh_b, 0 * TK, tid); CP_COMMIT();
    stage_k(smb + 1 * BUFB, xh_b, 1 * TK, tid); CP_COMMIT();
    stage_k(smb + 2 * BUFB, xh_b, 2 * TK, tid); CP_COMMIT();

    CP_WAIT(3);          // Q landed
    __syncthreads();

    uint32_t QH[4][4];
    {
        int rowq = wid * 16 + (q2 & 1) * 8 + rr;
        uint32_t base = qstage + rowq * 128;
        #pragma unroll
        for (int kc = 0; kc < 4; kc++) {
            uint32_t ch = (uint32_t)((((q2 >> 1) + 2 * kc) ^ rr) << 4);
            ldsm_x4(QH[kc], base + ch);
        }
    }

    Ctx c;
    c.kb_row = (uint32_t)(((q2 >> 1) * 8 + rr) * 128);
    c.vb_row = (uint32_t)(((q2 & 1) * 8 + rr) * 128);
    #pragma unroll
    for (int i = 0; i < 4; i++) {
        c.kch[i] = (uint32_t)((((q2 & 1) + 2 * i) ^ rr) << 4);
        c.vch[i] = (uint32_t)((((q2 >> 1) + 2 * i) ^ rr) << 4);
    }
    c.QH = QH;

    float O[8][4];
    #pragma unroll
    for (int i = 0; i < 8; i++)
        #pragma unroll
        for (int j = 0; j < 4; j++) O[i][j] = 0.f;
    float l0 = 0.f, l1 = 0.f;

    for (int tile = 0; tile < NTILE; tile++) {
        CP_WAIT(2);
        __syncthreads();

        if (tile + 3 < NTILE)
            stage_k(smb + ((tile + 3) & 3) * BUFB, xh_b, (tile + 3) * TK, tid);
        CP_COMMIT();

        c.buf = smb + (tile & 3) * BUFB;

        if (wg == 0) {
            quarter(c, 0, nm0, nm1, l0, l1, O);
            quarter(c, 1, nm0, nm1, l0, l1, O);
            quarter(c, 2, nm0, nm1, l0, l1, O);
            quarter(c, 3, nm0, nm1, l0, l1, O);
        } else {
            quarter(c, 2, nm0, nm1, l0, l1, O);
            quarter(c, 3, nm0, nm1, l0, l1, O);
            quarter(c, 0, nm0, nm1, l0, l1, O);
            quarter(c, 1, nm0, nm1, l0, l1, O);
        }
    }

    // ---- Epilogue ----
    l0 += __shfl_xor_sync(0xffffffffu, l0, 1);
    l0 += __shfl_xor_sync(0xffffffffu, l0, 2);
    l1 += __shfl_xor_sync(0xffffffffu, l1, 1);
    l1 += __shfl_xor_sync(0xffffffffu, l1, 2);
    const float inv0 = 1.f / l0;
    const float inv1 = 1.f / l1;

    const int row0 = q0 + wid * 16 + g;
    float* y0 = Y + ((size_t)b * SEQ + row0) * DIM + 2 * sg;
    float* y1 = y0 + 8 * DIM;
    #pragma unroll
    for (int jb = 0; jb < 8; jb++) {
        *(float2*)(y0 + jb * 8) = make_float2(O[jb][0] * inv0, O[jb][1] * inv0);
        *(float2*)(y1 + jb * 8) = make_float2(O[jb][2] * inv1, O[jb][3] * inv1);
    }
}

extern "C" void kernel_launch(void* const* d_in, const int* in_sizes, int n_in,
                              void* d_out, int out_size) {
    const float* X = (const float*)d_in[0];
    float* Y = (float*)d_out;

    prep_kernel<<<BATCH * SEQ * 8 / 256, 256>>>(X);

    cudaFuncSetAttribute(attn_hmma_kernel,
                         cudaFuncAttributeMaxDynamicSharedMemorySize, SMEM_BYTES);
    dim3 grid(SEQ / TQ, BATCH);
    attn_hmma_kernel<<<grid, 256, SMEM_BYTES>>>(X, Y);
}

// round 17
// speedup vs baseline: 1.0026x; 1.0026x over previous
#include <cuda_runtime.h>
#include <cuda_fp16.h>
#include <cstdint>
#include <math.h>

#define BATCH 8
#define SEQ   4096
#define DIM   64
#define TQ    128
#define TK    128
#define NTILE (SEQ / TK)

#define BUFB  16384              // per K buffer: 128 rows x 128B fp16
#define QSTG  (4 * BUFB)         // Q staging after the 4 K buffers
#define SMEM_BYTES (4 * BUFB + 16384)   // 81920 -> 2 CTAs/SM

#define L2E 1.44269504f

__device__ __align__(16) __half g_xh[BATCH * SEQ * DIM];   // fp16(X)
__device__ float g_qn[BATCH * SEQ];

static __device__ __forceinline__ uint32_t smem_u32(const void* p) {
    uint32_t a;
    asm("{ .reg .u64 t; cvta.to.shared.u64 t, %1; cvt.u32.u64 %0, t; }" : "=r"(a) : "l"(p));
    return a;
}
static __device__ __forceinline__ void cp16(uint32_t dst, const void* src) {
    asm volatile("cp.async.cg.shared.global [%0], [%1], 16;" :: "r"(dst), "l"(src) : "memory");
}
#define CP_COMMIT() asm volatile("cp.async.commit_group;" ::: "memory")
#define CP_WAIT(n)  asm volatile("cp.async.wait_group %0;" :: "n"(n) : "memory")

static __device__ __forceinline__ void ldsm_x4(uint32_t (&r)[4], uint32_t a) {
    asm volatile("ldmatrix.sync.aligned.m8n8.x4.shared.b16 {%0,%1,%2,%3}, [%4];"
                 : "=r"(r[0]), "=r"(r[1]), "=r"(r[2]), "=r"(r[3]) : "r"(a));
}
static __device__ __forceinline__ void ldsm_x4_t(uint32_t (&r)[4], uint32_t a) {
    asm volatile("ldmatrix.sync.aligned.m8n8.x4.trans.shared.b16 {%0,%1,%2,%3}, [%4];"
                 : "=r"(r[0]), "=r"(r[1]), "=r"(r[2]), "=r"(r[3]) : "r"(a));
}
static __device__ __forceinline__ void mma_f16(float (&d)[4], const uint32_t (&a)[4],
                                               uint32_t b0, uint32_t b1) {
    asm volatile("mma.sync.aligned.m16n8k16.row.col.f32.f16.f16.f32 "
                 "{%0,%1,%2,%3}, {%4,%5,%6,%7}, {%8,%9}, {%0,%1,%2,%3};"
                 : "+f"(d[0]), "+f"(d[1]), "+f"(d[2]), "+f"(d[3])
                 : "r"(a[0]), "r"(a[1]), "r"(a[2]), "r"(a[3]), "r"(b0), "r"(b1));
}
static __device__ __forceinline__ float ex2f(float z) {
    float p;
    asm("ex2.approx.f32 %0, %1;" : "=f"(p) : "f"(z));
    return p;
}
static __device__ __forceinline__ uint32_t pack_h2(float a, float b) {
    __half2 h = __float22half2_rn(make_float2(a, b));
    return *reinterpret_cast<uint32_t*>(&h);
}

// ---- Pre-pass: X -> fp16 + row norms. 8 threads/row. ----
__global__ void prep_kernel(const float* __restrict__ X) {
    int t = blockIdx.x * 256 + threadIdx.x;
    int ln = t & 7;
    const float4* p = (const float4*)(X + (size_t)(t >> 3) * DIM) + ln * 2;
    float4 a = p[0], b = p[1];
    uint32_t h0 = pack_h2(a.x, a.y), h1 = pack_h2(a.z, a.w);
    uint32_t h2 = pack_h2(b.x, b.y), h3 = pack_h2(b.z, b.w);
    ((uint2*)g_xh)[2*t]   = make_uint2(h0, h1);
    ((uint2*)g_xh)[2*t+1] = make_uint2(h2, h3);
    float s = a.x*a.x + a.y*a.y + a.z*a.z + a.w*a.w
            + b.x*b.x + b.y*b.y + b.z*b.z + b.w*b.w;
    s += __shfl_xor_sync(0xffffffffu, s, 1, 8);
    s += __shfl_xor_sync(0xffffffffu, s, 2, 8);
    s += __shfl_xor_sync(0xffffffffu, s, 4, 8);
    if (ln == 0) g_qn[t >> 3] = s;
}

// stage one K tile (16KB fp16, 128 rows) via cp.async; 4 chunks/thread
static __device__ __forceinline__ void stage_k(uint32_t buf, const __half* xh_b,
                                               int kt, int tid) {
    #pragma unroll
    for (int k = 0; k < 4; k++) {
        int cid = tid + k * 256;
        int row = cid >> 3, c = cid & 7;
        uint32_t doff = (uint32_t)(row * 128 + ((c ^ (row & 7)) << 4));
        size_t soff = (size_t)(kt + row) * 128 + c * 16;
        cp16(buf + doff, (const char*)xh_b + soff);
    }
}

struct Ctx {
    uint32_t buf, kb_row, vb_row;
    uint32_t kch[4], vch[4];
    const uint32_t (*QH)[4];
};

// S = Q K^T for quarter h (rows h*32..h*32+31 of the 128-row tile)
static __device__ __forceinline__ void compute_S(const Ctx& c, int h, float (&S)[4][4]) {
    #pragma unroll
    for (int i = 0; i < 4; i++)
        #pragma unroll
        for (int j = 0; j < 4; j++) S[i][j] = 0.f;
    #pragma unroll
    for (int kc = 0; kc < 4; kc++) {
        #pragma unroll
        for (int j2 = 0; j2 < 2; j2++) {
            int j = 2 * h + j2;
            uint32_t a = c.buf + c.kb_row + (uint32_t)(j * 2048) + c.kch[kc];
            uint32_t bh[4];
            ldsm_x4(bh, a);
            mma_f16(S[2*j2],   c.QH[kc], bh[0], bh[1]);
            mma_f16(S[2*j2+1], c.QH[kc], bh[2], bh[3]);
        }
    }
}

// p = exp2(fma(s, L2E, -m*L2E)) -> fp16; l accumulates fp32 exps
static __device__ __forceinline__ void softmax_q(const float (&S)[4][4], float nm0, float nm1,
                                                 float& l0, float& l1, uint32_t (&PH)[4][2]) {
    #pragma unroll
    for (int jb = 0; jb < 4; jb++) {
        float e0 = ex2f(fmaf(S[jb][0], L2E, nm0));
        float e1 = ex2f(fmaf(S[jb][1], L2E, nm0));
        float e2 = ex2f(fmaf(S[jb][2], L2E, nm1));
        float e3 = ex2f(fmaf(S[jb][3], L2E, nm1));
        l0 += e0 + e1;
        l1 += e2 + e3;
        PH[jb][0] = pack_h2(e0, e1);
        PH[jb][1] = pack_h2(e2, e3);
    }
}

// O += P * V for quarter h
static __device__ __forceinline__ void compute_O(const Ctx& c, int h,
                                                 const uint32_t (&PH)[4][2], float (&O)[8][4]) {
    #pragma unroll
    for (int n2 = 0; n2 < 2; n2++) {
        int nc = 2 * h + n2;
        uint32_t pah[4] = {PH[2*n2][0], PH[2*n2][1], PH[2*n2+1][0], PH[2*n2+1][1]};
        #pragma unroll
        for (int cp = 0; cp < 4; cp++) {
            uint32_t a = c.buf + c.vb_row + (uint32_t)(nc * 2048) + c.vch[cp];
            uint32_t bh[4];
            ldsm_x4_t(bh, a);
            mma_f16(O[2*cp],   pah, bh[0], bh[1]);
            mma_f16(O[2*cp+1], pah, bh[2], bh[3]);
        }
    }
}

static __device__ __forceinline__ void quarter(const Ctx& c, int h, float nm0, float nm1,
                                               float& l0, float& l1, float (&O)[8][4]) {
    float S[4][4];
    uint32_t PH[4][2];
    compute_S(c, h, S);
    softmax_q(S, nm0, nm1, l0, l1, PH);
    compute_O(c, h, PH, O);
}

__global__ __launch_bounds__(256, 2)
void attn_hmma_kernel(const float* __restrict__ X, float* __restrict__ Y) {
    extern __shared__ char smc[];
    const uint32_t smb = smem_u32(smc);

    const int tid  = threadIdx.x;
    const int wid  = tid >> 5;
    const int lane = tid & 31;
    const int q2   = lane >> 3;
    const int rr   = lane & 7;
    const int g    = lane >> 2;
    const int sg   = lane & 3;
    const int wg   = wid >> 2;

    const int b  = blockIdx.y;
    const int q0 = blockIdx.x * TQ;
    const __half* xh_b = g_xh + (size_t)b * SEQ * DIM;

    const float nm0 = -g_qn[b * SEQ + q0 + wid * 16 + g] * L2E;
    const float nm1 = -g_qn[b * SEQ + q0 + wid * 16 + g + 8] * L2E;

    // ---- Stage Q tile (16KB) ----
    const uint32_t qstage = smb + QSTG;
    #pragma unroll
    for (int k = 0; k < 4; k++) {
        int cid = tid + k * 256;
        int row = cid >> 3, c = cid & 7;
        uint32_t doff = (uint32_t)(row * 128 + ((c ^ (row & 7)) << 4));
        size_t soff = (size_t)(q0 + row) * 128 + c * 16;
        cp16(qstage + doff, (const char*)xh_b + soff);
    }
    CP_COMMIT();

    // ---- Preload K tiles 0..2 ----
    stage_k(smb + 0 * BUFB, xh_b, 0 * TK, tid); CP_COMMIT();
    stage_k(smb + 1 * BUFB, xh_b, 1 * TK, tid); CP_COMMIT();
    stage_k(smb + 2 * BUFB, xh_b, 2 * TK, tid); CP_COMMIT();

    CP_WAIT(3);          // Q landed
    __syncthreads();

    uint32_t QH[4][4];
    {
        int rowq = wid * 16 + (q2 & 1) * 8 + rr;
        uint32_t base = qstage + rowq * 128;
        #pragma unroll
        for (int kc = 0; kc < 4; kc++) {
            uint32_t ch = (uint32_t)((((q2 >> 1) + 2 * kc) ^ rr) << 4);
            ldsm_x4(QH[kc], base + ch);
        }
    }

    Ctx c;
    c.kb_row = (uint32_t)(((q2 >> 1) * 8 + rr) * 128);
    c.vb_row = (uint32_t)(((q2 & 1) * 8 + rr) * 128);
    #pragma unroll
    for (int i = 0; i < 4; i++) {
        c.kch[i] = (uint32_t)((((q2 & 1) + 2 * i) ^ rr) << 4);
        c.vch[i] = (uint32_t)((((q2 >> 1) + 2 * i) ^ rr) << 4);
    }
    c.QH = QH;

    float O[8][4];
    #pragma unroll
    for (int i = 0; i < 8; i++)
        #pragma unroll
        for (int j = 0; j < 4; j++) O[i][j] = 0.f;
    float l0 = 0.f, l1 = 0.f;

    for (int tile = 0; tile < NTILE; tile++) {
        CP_WAIT(2);
        __syncthreads();

        if (tile + 3 < NTILE)
            stage_k(smb + ((tile + 3) & 3) * BUFB, xh_b, (tile + 3) * TK, tid);
        CP_COMMIT();

        c.buf = smb + (tile & 3) * BUFB;

        if (wg == 0) {
            quarter(c, 0, nm0, nm1, l0, l1, O);
            quarter(c, 1, nm0, nm1, l0, l1, O);
            quarter(c, 2, nm0, nm1, l0, l1, O);
            quarter(c, 3, nm0, nm1, l0, l1, O);
        } else {
            quarter(c, 2, nm0, nm1, l0, l1, O);
            quarter(c, 3, nm0, nm1, l0, l1, O);
            quarter(c, 0, nm0, nm1, l0, l1, O);
            quarter(c, 1, nm0, nm1, l0, l1, O);
        }
    }

    // ---- Epilogue ----
    l0 += __shfl_xor_sync(0xffffffffu, l0, 1);
    l0 += __shfl_xor_sync(0xffffffffu, l0, 2);
    l1 += __shfl_xor_sync(0xffffffffu, l1, 1);
    l1 += __shfl_xor_sync(0xffffffffu, l1, 2);
    const float inv0 = 1.f / l0;
    const float inv1 = 1.f / l1;

    const int row0 = q0 + wid * 16 + g;
    float* y0 = Y + ((size_t)b * SEQ + row0) * DIM + 2 * sg;
    float* y1 = y0 + 8 * DIM;
    #pragma unroll
    for (int jb = 0; jb < 8; jb++) {
        *(float2*)(y0 + jb * 8) = make_float2(O[jb][0] * inv0, O[jb][1] * inv0);
        *(float2*)(y1 + jb * 8) = make_float2(O[jb][2] * inv1, O[jb][3] * inv1);
    }
}

extern "C" void kernel_launch(void* const* d_in, const int* in_sizes, int n_in,
                              void* d_out, int out_size) {
    const float* X = (const float*)d_in[0];
    float* Y = (float*)d_out;

    prep_kernel<<<BATCH * SEQ * 8 / 256, 256>>>(X);

    cudaFuncSetAttribute(attn_hmma_kernel,
                         cudaFuncAttributeMaxDynamicSharedMemorySize, SMEM_BYTES);
    dim3 grid(SEQ / TQ, BATCH);
    attn_hmma_kernel<<<grid, 256, SMEM_BYTES>>>(X, Y);
}